// round 15
// baseline (speedup 1.0000x reference)
#include <cuda_runtime.h>
#include <cuda_fp16.h>
#include <math.h>
#include <stdint.h>

#define NL 2
#define NB 64
#define NT 256
#define NI 512
#define NH 1024
#define NO 256
#define G4 4096
#define MROWS (NB*NT)   // 16384
#define NCTA 128

// ---------------- scratch (device globals) ----------------
__device__ __align__(16) float g_pre0[(size_t)NT*NB*G4];   // [t][b][4H] fp32 (batch space)
__device__ __align__(16) float g_c0[NB*NH], g_c1[NB*NH];   // sorted space
__device__ __align__(16) float g_h0f[NB*NH], g_h1f[NB*NH]; // sorted space
__device__ __align__(16) __half g_h0h[2][NB*NH];   // [ping] sorted space
__device__ __align__(16) __half g_h1h[2][NB*NH];
__device__ __align__(16) __half g_h0in[2][NB*NH];  // [t&1] sorted space
__device__ __align__(16) __half g_w0p[(size_t)G4*NH];       // reordered Whh0 (fp16)
__device__ __align__(16) __half g_w1p[(size_t)G4*2*NH];     // reordered [Wih1|Whh1] (fp16)
// length-sort metadata
__device__ int g_perm[NB];
__device__ int g_Lcs[NB];
__device__ int g_nblkE[NT];
// big-GEMM operands
__device__ __align__(16) __half g_xh[(size_t)MROWS*NI];
__device__ __align__(16) __half g_wih0s[(size_t)G4*NI];
__device__ __align__(16) __half g_w1s[(size_t)NH*NH];
__device__ __align__(16) __half g_w2s[(size_t)NO*NH];
__device__ __align__(16) __half g_louth[(size_t)MROWS*NH];  // batch space rows m=b*256+t
__device__ __align__(16) __half g_fc1h[(size_t)MROWS*NH];
// global barrier state
__device__ unsigned g_gen = 0;
__device__ unsigned g_cnt = 0;

// ---------------- low-level helpers ----------------
__device__ __forceinline__ uint32_t smem_u32(const void* p) {
    uint32_t a;
    asm("{ .reg .u64 t; cvta.to.shared.u64 t, %1; cvt.u32.u64 %0, t; }" : "=r"(a) : "l"(p));
    return a;
}
__device__ __forceinline__ void cpa16(uint32_t dst, const void* src) {
    asm volatile("cp.async.cg.shared.global [%0], [%1], 16;" :: "r"(dst), "l"(src) : "memory");
}
__device__ __forceinline__ void sts128(uint32_t addr, uint4 v) {
    asm volatile("st.shared.v4.b32 [%0], {%1,%2,%3,%4};"
                 :: "r"(addr), "r"(v.x), "r"(v.y), "r"(v.z), "r"(v.w) : "memory");
}
__device__ __forceinline__ void ldmx4(uint32_t* r, uint32_t addr) {
    asm volatile("ldmatrix.sync.aligned.m8n8.x4.shared.b16 {%0,%1,%2,%3}, [%4];"
                 : "=r"(r[0]), "=r"(r[1]), "=r"(r[2]), "=r"(r[3]) : "r"(addr));
}
__device__ __forceinline__ void mma16816(float (&d)[4], const uint32_t* a, const uint32_t* b) {
    asm volatile("mma.sync.aligned.m16n8k16.row.col.f32.f16.f16.f32 "
        "{%0,%1,%2,%3}, {%4,%5,%6,%7}, {%8,%9}, {%0,%1,%2,%3};"
        : "+f"(d[0]), "+f"(d[1]), "+f"(d[2]), "+f"(d[3])
        : "r"(a[0]), "r"(a[1]), "r"(a[2]), "r"(a[3]), "r"(b[0]), "r"(b[1]));
}
__device__ __forceinline__ float sigf(float x)  { return 1.f / (1.f + __expf(-x)); }
__device__ __forceinline__ float tanhft(float x){ return 2.f / (1.f + __expf(-2.f * x)) - 1.f; }

__device__ __forceinline__ unsigned ld_acq(const unsigned* p) {
    unsigned v;
    asm volatile("ld.acquire.gpu.global.u32 %0, [%1];" : "=r"(v) : "l"(p) : "memory");
    return v;
}
// generation barrier; all NCTA CTAs resident
__device__ __forceinline__ void gbar() {
    __syncthreads();
    if (threadIdx.x == 0) {
        unsigned old = ld_acq(&g_gen);
        __threadfence();
        unsigned arr = atomicAdd(&g_cnt, 1u);
        if (arr == NCTA - 1) {
            g_cnt = 0;
            __threadfence();
            atomicAdd(&g_gen, 1u);
        } else {
            while (ld_acq(&g_gen) == old) {}
        }
        __threadfence();
    }
    __syncthreads();
}

// ---------------- sort: perm by clamped length desc + per-step regime ----------------
__global__ void sort_kernel(const int* __restrict__ lens)
{
    __shared__ int Lc[NB], pm[NB], Ls[NB];
    int tid = threadIdx.x;
    if (tid < NB) {
        int L = lens[tid]; if (L < 1) L = 1;
        Lc[tid] = L;
    }
    __syncthreads();
    if (tid < NB) {
        int L = Lc[tid];
        int r = 0;
        for (int j = 0; j < NB; j++) {
            int Lj = Lc[j];
            if (Lj > L || (Lj == L && j < tid)) r++;
        }
        pm[r] = tid;
        Ls[r] = L;
    }
    __syncthreads();
    if (tid < NB) { g_perm[tid] = pm[tid]; g_Lcs[tid] = Ls[tid]; }
    for (int t = tid; t < NT; t += blockDim.x) {
        int a = 0;
        for (int i = 0; i < NB; i++) a += (Ls[i] > t);
        int nb = (a + 15) >> 4;
        if (nb < 1) nb = 1;
        g_nblkE[t] = (nb >= 3) ? 4 : nb;
    }
}

// ---------------- init: weighted hidden + cell copy + fp16 state (sorted space) ----------------
__global__ void init_state_kernel(const float* __restrict__ clstm,
                                  const float* __restrict__ hidden,
                                  const float* __restrict__ cell,
                                  const int* __restrict__ lens)
{
    int l = blockIdx.x >> 6;
    int s = blockIdx.x & 63;
    int b = g_perm[s];
    const float* cl = clstm + (size_t)b * NH;
    const float* hd = hidden + ((size_t)l * NB + b) * NH;
    const float* ce = cell   + ((size_t)l * NB + b) * NH;

    float cmn = 3.4e38f, cmx = -3.4e38f, hmn = 3.4e38f, hmx = -3.4e38f;
    for (int h = threadIdx.x; h < NH; h += 256) {
        float cv = cl[h], hv = hd[h];
        cmn = fminf(cmn, cv); cmx = fmaxf(cmx, cv);
        hmn = fminf(hmn, hv); hmx = fmaxf(hmx, hv);
    }
#pragma unroll
    for (int o = 16; o; o >>= 1) {
        cmn = fminf(cmn, __shfl_xor_sync(0xffffffffu, cmn, o));
        cmx = fmaxf(cmx, __shfl_xor_sync(0xffffffffu, cmx, o));
        hmn = fminf(hmn, __shfl_xor_sync(0xffffffffu, hmn, o));
        hmx = fmaxf(hmx, __shfl_xor_sync(0xffffffffu, hmx, o));
    }
    __shared__ float sm[4][8];
    __shared__ float fs[4];
    int w = threadIdx.x >> 5, ln = threadIdx.x & 31;
    if (ln == 0) { sm[0][w] = cmn; sm[1][w] = cmx; sm[2][w] = hmn; sm[3][w] = hmx; }
    __syncthreads();
    if (threadIdx.x < 4) {
        float v = sm[threadIdx.x][0];
        bool ismin = (threadIdx.x == 0) || (threadIdx.x == 2);
#pragma unroll
        for (int i = 1; i < 8; i++) {
            float x = sm[threadIdx.x][i];
            v = ismin ? fminf(v, x) : fmaxf(v, x);
        }
        fs[threadIdx.x] = v;
    }
    __syncthreads();
    cmn = fs[0]; cmx = fs[1]; hmn = fs[2]; hmx = fs[3];
    float crange = cmx - cmn, hrange = hmx - hmn;
    bool lz = (lens[b] == 0);

    float* hf = l ? g_h1f : g_h0f;
    float* cf = l ? g_c1  : g_c0;
    __half* hh = l ? g_h1h[0] : g_h0h[0];

    for (int h = threadIdx.x; h < NH; h += 256) {
        float cv = cl[h], hv = hd[h];
        float s1 = (crange > 0.f) ? (cv - cmn) / crange : cv;
        float s2 = (hrange > 0.f) ? (hmn + s1 * hrange) : s1;
        float c  = lz ? cv : s2;
        float hw = 0.5f * hv + 0.5f * c;
        size_t off = (size_t)s * NH + h;
        hf[off] = hw;
        cf[off] = ce[h];
        hh[off] = __float2half(hw);
    }
}

// ---------------- step-weight prep: 32 rows/blk, unit-major (uu=r>>2, g=r&3), fp16 ----------------
__global__ void prep_w0_kernel(const float* __restrict__ w)
{
    int idx = blockIdx.x * 256 + threadIdx.x;
    int k = (idx & 255) * 4;
    int row = idx >> 8;
    int blk = row >> 5, r = row & 31;
    int uu = r >> 2, g = r & 3;
    int srow = g * NH + blk * 8 + uu;
    float4 v = *(const float4*)(w + (size_t)srow * NH + k);
    size_t o = (size_t)row * NH + k;
    g_w0p[o + 0] = __float2half(v.x);
    g_w0p[o + 1] = __float2half(v.y);
    g_w0p[o + 2] = __float2half(v.z);
    g_w0p[o + 3] = __float2half(v.w);
}

__global__ void prep_w1_kernel(const float* __restrict__ wih, const float* __restrict__ whh)
{
    int idx = blockIdx.x * 256 + threadIdx.x;
    int k = (idx & 511) * 4;
    int row = idx >> 9;
    int blk = row >> 5, r = row & 31;
    int uu = r >> 2, g = r & 3;
    int srow = g * NH + blk * 8 + uu;
    const float* src = (k < NH) ? (wih + (size_t)srow * NH + k)
                                : (whh + (size_t)srow * NH + (k - NH));
    float4 v = *(const float4*)src;
    size_t o = (size_t)row * (2 * NH) + k;
    g_w1p[o + 0] = __float2half(v.x);
    g_w1p[o + 1] = __float2half(v.y);
    g_w1p[o + 2] = __float2half(v.z);
    g_w1p[o + 3] = __float2half(v.w);
}

// ---------------- fp32 -> fp16 ----------------
__global__ void conv_w_kernel(const float* __restrict__ src, __half* __restrict__ dst)
{
    size_t i = ((size_t)blockIdx.x * 256 + threadIdx.x) * 4;
    float4 v = *(const float4*)(src + i);
    dst[i + 0] = __float2half(v.x);
    dst[i + 1] = __float2half(v.y);
    dst[i + 2] = __float2half(v.z);
    dst[i + 3] = __float2half(v.w);
}

// ---------------- x conversion with reorder: row m = t*64+b ----------------
__global__ void conv_x_kernel(const float* __restrict__ x)
{
    int idx = blockIdx.x * 256 + threadIdx.x;
    int kq = idx & 127;
    int m = idx >> 7;
    int t = m >> 6, b = m & 63;
    float4 v = *(const float4*)(x + ((size_t)b * NT + t) * NI + kq * 4);
    size_t o = (size_t)m * NI + kq * 4;
    g_xh[o + 0] = __float2half(v.x);
    g_xh[o + 1] = __float2half(v.y);
    g_xh[o + 2] = __float2half(v.z);
    g_xh[o + 3] = __float2half(v.w);
}

// ---------------- big MMA GEMM: plain fp16 (unchanged from R14) ----------------
#define GSTAGE 20480
#define GEMM_SMEM (2*GSTAGE)

template<int EP>
__global__ void __launch_bounds__(256) mma_gemm_kernel(
    const __half* __restrict__ A, const __half* __restrict__ W,
    const float* __restrict__ bias, const float* __restrict__ bias2,
    float* __restrict__ Cf, __half* __restrict__ Ch,
    int N, int K, const int* __restrict__ lens)
{
    extern __shared__ char smem[];
    const uint32_t sb = smem_u32(smem);
    const int tid = threadIdx.x;
    const int lane = tid & 31, wid = tid >> 5;
    const int wm = wid & 3, wn = wid >> 2;
    const int n0 = blockIdx.x * 128;
    const int m0 = blockIdx.y * 128;
    const int KC = K >> 5;

    float acc[2][8][4] = {};

    auto issue_load = [&](int c, int stg) {
        const int k0 = c << 5;
        uint32_t base = sb + (uint32_t)stg * GSTAGE;
#pragma unroll
        for (int i = 0; i < 4; i++) {
            int s = tid + (i << 8);
            int p = s >> 9;
            int r = (s >> 2) & 127;
            int seg = s & 3;
            const __half* src = (p == 0) ? A + (size_t)(m0 + r) * K + k0 + seg * 8
                                         : W + (size_t)(n0 + r) * K + k0 + seg * 8;
            cpa16(base + (uint32_t)(p * 10240 + r * 80 + seg * 16), src);
        }
        asm volatile("cp.async.commit_group;" ::: "memory");
    };

    issue_load(0, 0);

    const uint32_t a_base = (uint32_t)((wm * 32 + (lane & 15)) * 80 + (lane >> 4) * 16);
    const uint32_t w_base = (uint32_t)((wn * 64 + (lane & 7) + ((lane >> 4) << 3)) * 80
                                       + ((lane >> 3) & 1) * 16);

    for (int c = 0; c < KC; c++) {
        if (c + 1 < KC) {
            issue_load(c + 1, (c + 1) & 1);
            asm volatile("cp.async.wait_group 1;" ::: "memory");
        } else {
            asm volatile("cp.async.wait_group 0;" ::: "memory");
        }
        __syncthreads();

        uint32_t Ah = sb + (uint32_t)((c & 1) * GSTAGE);
        uint32_t Wh = Ah + 10240;
#pragma unroll
        for (int kk = 0; kk < 2; kk++) {
            uint32_t kb = (uint32_t)kk * 32;
            uint32_t ah[2][4], wh[16];
#pragma unroll
            for (int sub = 0; sub < 2; sub++)
                ldmx4(ah[sub], Ah + a_base + sub * 16 * 80 + kb);
#pragma unroll
            for (int q = 0; q < 4; q++)
                ldmx4(wh + q * 4, Wh + w_base + q * 16 * 80 + kb);
#pragma unroll
            for (int sub = 0; sub < 2; sub++)
#pragma unroll
                for (int nq = 0; nq < 8; nq++)
                    mma16816(acc[sub][nq], ah[sub], wh + nq * 2);
        }
        __syncthreads();
    }

#pragma unroll
    for (int sub = 0; sub < 2; sub++) {
        int r0 = m0 + wm * 32 + sub * 16 + (lane >> 2);
#pragma unroll
        for (int nq = 0; nq < 8; nq++) {
            int c0 = n0 + wn * 64 + nq * 8 + (lane & 3) * 2;
            float b0 = bias[c0], b1 = bias[c0 + 1];
            if (EP == 0) { b0 += bias2[c0]; b1 += bias2[c0 + 1]; }
#pragma unroll
            for (int half_ = 0; half_ < 2; half_++) {
                int r = r0 + half_ * 8;
                float v0 = acc[sub][nq][half_ * 2]     + b0;
                float v1 = acc[sub][nq][half_ * 2 + 1] + b1;
                if (EP >= 1) { v0 = fmaxf(v0, 0.f); v1 = fmaxf(v1, 0.f); }
                if (EP == 2) {
                    if (lens[r >> 8] == 0) { v0 = 0.f; v1 = 0.f; }
                }
                if (EP == 1) {
                    __half2 hp; hp.x = __float2half(v0); hp.y = __float2half(v1);
                    *(__half2*)&Ch[(size_t)r * N + c0] = hp;
                } else {
                    float2 o; o.x = v0; o.y = v1;
                    *(float2*)&Cf[(size_t)r * N + c0] = o;
                }
            }
        }
    }
}

// ---------------- persistent LSTM: smem weights, dynamic-M regimes, 1 barrier/step ----------------
#define A_STG 16384
#define SB_W0 (2*A_STG)           // 32768
#define SB_W1 (SB_W0 + 65536)     // 98304
#define PERSIST_SMEM (SB_W1 + 131072)  // 229376 (224 KB)

// One sub-step GEMM for the CTA's 32 gate rows over active M-blocks.
// NBLKE in {4,2,1}; NBLKE==4 = R14 path (shuffle routing); else split-K + smem routing.
template<int LAYER, int NBLKE>
__device__ __forceinline__ void step_core(
    char* smemc, uint32_t sb, int tid, int lane, int wid,
    int ping, int hpar, int s_row, int wn_own, float (&gq)[2][4])
{
    constexpr int NCH = LAYER ? 16 : 8;
    constexpr int NITEMS = 2 * NBLKE;
    constexpr int LOGNI = (NBLKE == 4) ? 3 : (NBLKE == 2) ? 2 : 1;
    constexpr int NKQ = NITEMS;
    constexpr int NSPLIT = 8 / NITEMS;
    const uint32_t wbase = sb + (LAYER ? SB_W1 : SB_W0);

    int mb, wnp, kq0, ks;
    if (NBLKE == 4) { mb = wid & 3; wnp = wid >> 2; kq0 = 0; ks = 0; }
    else {
        int item = wid & (NITEMS - 1);
        ks = wid >> LOGNI;
        mb = item >> 1; wnp = item & 1;
        kq0 = ks * NKQ;
    }

    const uint32_t arow = (uint32_t)(mb * 16 + (lane & 15));
    const uint32_t arow256 = arow * 256;
    const uint32_t aseg = (uint32_t)(lane >> 4);
    const uint32_t akey = arow & 7;
    const uint32_t wrow = (uint32_t)(wnp * 16 + (lane & 7) + ((lane >> 4) << 3));
    const uint32_t wrow128 = wrow * 128;
    const uint32_t wsub = (uint32_t)(((lane >> 3) & 1) * 16);
    const uint32_t wsw = (wrow & 7) << 4;

    float d[2][4] = {};

    auto issue_load = [&](int c, int stg) {
        const __half* a0;
        if (LAYER == 0)      a0 = g_h0h[ping] + c * 128;
        else if (c < 8)      a0 = g_h0in[hpar] + c * 128;
        else                 a0 = g_h1h[ping] + (c - 8) * 128;
        uint32_t base = sb + (uint32_t)stg * A_STG;
#pragma unroll
        for (int i = 0; i < 4; i++) {
            int q = tid + (i << 8);
            int r = q >> 4, sg = q & 15;
            if (NBLKE == 4 || r < NBLKE * 16)
                cpa16(base + (uint32_t)(r * 256 + (((sg ^ (r & 7)) << 4))),
                      a0 + (size_t)r * NH + sg * 8);
        }
        asm volatile("cp.async.commit_group;" ::: "memory");
    };

    issue_load(0, 0);

#pragma unroll 1
    for (int c = 0; c < NCH; c++) {
        asm volatile("cp.async.wait_group 0;" ::: "memory");
        __syncthreads();
        if (c + 1 < NCH) issue_load(c + 1, (c + 1) & 1);

        uint32_t Ab = sb + (uint32_t)((c & 1) * A_STG);
        uint32_t Wb = wbase + (uint32_t)(c * 8192);
#pragma unroll
        for (int i = 0; i < NKQ; i++) {
            int kq = kq0 + i;
            uint32_t aaddr = Ab + arow256 + ((((uint32_t)(kq << 1) + aseg) ^ akey) << 4);
            uint32_t waddr = Wb + (uint32_t)((kq >> 2) * 4096) + wrow128
                           + (((uint32_t)((kq & 3) * 32) + wsub) ^ wsw);
            uint32_t ah[4], wh[4];
            ldmx4(ah, aaddr);
            ldmx4(wh, waddr);
            mma16816(d[0], ah, wh);
            mma16816(d[1], ah, wh + 2);
        }
    }

    if (NBLKE == 4) {
        // register-only quad-pair routing (R14 path)
#pragma unroll
        for (int nq = 0; nq < 2; nq++) {
            float s0 = (lane & 1) ? d[nq][0] : d[nq][2];
            float s1 = (lane & 1) ? d[nq][1] : d[nq][3];
            float r0 = __shfl_xor_sync(0xffffffffu, s0, 1);
            float r1 = __shfl_xor_sync(0xffffffffu, s1, 1);
            if (lane & 1) { gq[nq][2] = d[nq][2]; gq[nq][3] = d[nq][3]; gq[nq][0] = r0; gq[nq][1] = r1; }
            else          { gq[nq][0] = d[nq][0]; gq[nq][1] = d[nq][1]; gq[nq][2] = r0; gq[nq][3] = r1; }
        }
    } else {
        // deterministic split-K combine via per-ks smem buffers (overlay A stages)
        float* gates = (float*)smemc;                 // [NSPLIT][64][32]
        __syncthreads();                              // all warps done with A stages
        {
            int row0 = mb * 16 + (lane >> 2);
            int colb = wnp * 16 + (lane & 3) * 2;
            float* gk = gates + ks * 2048;
#pragma unroll
            for (int nq = 0; nq < 2; nq++) {
                int cb = colb + nq * 8;
                gk[row0 * 32 + cb]           = d[nq][0];
                gk[row0 * 32 + cb + 1]       = d[nq][1];
                gk[(row0 + 8) * 32 + cb]     = d[nq][2];
                gk[(row0 + 8) * 32 + cb + 1] = d[nq][3];
            }
        }
        __syncthreads();
#pragma unroll
        for (int nq = 0; nq < 2; nq++) {
            int uloc = wn_own * 4 + nq * 2 + ((lane & 3) >> 1);
            int idx = s_row * 32 + uloc * 4;
#pragma unroll
            for (int g = 0; g < 4; g++) {
                float acc = 0.f;
#pragma unroll
                for (int k = 0; k < NSPLIT; k++)
                    acc += gates[k * 2048 + idx + g];
                gq[nq][g] = acc;
            }
        }
        __syncthreads();   // protect gates region before next sub-step's stage-0 writes
    }
}

template<int LAYER>
__device__ __forceinline__ void run_step(
    char* smemc, uint32_t sb, int tid, int lane, int wid,
    int nblkE, int ping, int hpar, int s_row, int wn_own, float (&gq)[2][4])
{
    if (nblkE == 4)      step_core<LAYER, 4>(smemc, sb, tid, lane, wid, ping, hpar, s_row, wn_own, gq);
    else if (nblkE == 2) step_core<LAYER, 2>(smemc, sb, tid, lane, wid, ping, hpar, s_row, wn_own, gq);
    else                 step_core<LAYER, 1>(smemc, sb, tid, lane, wid, ping, hpar, s_row, wn_own, gq);
}

__global__ void __launch_bounds__(256) lstm_persist_kernel(
    const int* __restrict__ lens,
    const float* __restrict__ pre0,
    const float* __restrict__ bih1, const float* __restrict__ bhh1,
    float* __restrict__ out_hn, float* __restrict__ out_cn)
{
    extern __shared__ char smem[];
    const uint32_t sb = smem_u32(smem);
    const int tid = threadIdx.x;
    const int lane = tid & 31, wid = tid >> 5;
    const int wm = wid & 3, wn = wid >> 2;
    const int blk = blockIdx.x;

    const int s_row = wm * 16 + (lane >> 2) + ((lane & 1) << 3);   // sorted row
    const int b = g_perm[s_row];                                    // batch row
    const int rawL = lens[b];
    const int L = g_Lcs[s_row];

    int u[2];
    u[0] = blk * 8 + wn * 4 + 0 * 2 + ((lane & 3) >> 1);
    u[1] = blk * 8 + wn * 4 + 1 * 2 + ((lane & 3) >> 1);

    // ---- cache both layers' weights in smem (once; 128B-row XOR layout) ----
    {
        const __half* w0 = g_w0p + (size_t)blk * 32 * NH;
#pragma unroll 4
        for (int idx = tid; idx < 4096; idx += 256) {
            int c = idx >> 8;
            int q = idx & 255;
            int r = q >> 3, seg = q & 7;
            uint4 v = *(const uint4*)(w0 + (size_t)r * NH + c * 64 + seg * 8);
            sts128(sb + SB_W0 + (uint32_t)(c * 4096 + r * 128 + ((seg * 16) ^ ((r & 7) << 4))), v);
        }
        const __half* w1 = g_w1p + (size_t)blk * 32 * 2 * NH;
#pragma unroll 4
        for (int idx = tid; idx < 8192; idx += 256) {
            int c = idx >> 8;
            int q = idx & 255;
            int r = q >> 3, seg = q & 7;
            uint4 v = *(const uint4*)(w1 + (size_t)r * 2 * NH + c * 64 + seg * 8);
            sts128(sb + SB_W1 + (uint32_t)(c * 4096 + r * 128 + ((seg * 16) ^ ((r & 7) << 4))), v);
        }
    }
    __syncthreads();

    // load initial states into registers
    float c0r[2], h0r[2], c1r[2], h1r[2];
    float bs1[2][4];
#pragma unroll
    for (int nq = 0; nq < 2; nq++) {
        size_t off = (size_t)s_row * NH + u[nq];
        c0r[nq] = g_c0[off]; h0r[nq] = g_h0f[off];
        c1r[nq] = g_c1[off]; h1r[nq] = g_h1f[off];
#pragma unroll
        for (int g = 0; g < 4; g++)
            bs1[nq][g] = bih1[g * NH + u[nq]] + bhh1[g * NH + u[nq]];
    }

    // ---- prologue: A(0) ----
    {
        float pf[2][4];
        const float* pb = pre0 + ((size_t)(0 * NB + b)) * G4;
#pragma unroll
        for (int nq = 0; nq < 2; nq++)
#pragma unroll
            for (int g = 0; g < 4; g++)
                pf[nq][g] = __ldg(pb + g * NH + u[nq]);
        float gq[2][4];
        run_step<0>(smem, sb, tid, lane, wid, __ldg(&g_nblkE[0]), 0, 0, s_row, wn, gq);
        const bool valid = (0 < L);
#pragma unroll
        for (int nq = 0; nq < 2; nq++) {
            float iv = sigf(gq[nq][0] + pf[nq][0]), fv = sigf(gq[nq][1] + pf[nq][1]);
            float gv = tanhft(gq[nq][2] + pf[nq][2]), ov = sigf(gq[nq][3] + pf[nq][3]);
            float cn = fv * c0r[nq] + iv * gv;
            float hn = ov * tanhft(cn);
            c0r[nq] = valid ? cn : c0r[nq];
            float hc = valid ? hn : h0r[nq];
            h0r[nq] = hc;
            float hin = valid ? hn : 0.f;
            size_t off = (size_t)s_row * NH + u[nq];
            g_h0h[1][off] = __float2half(hc);
            g_h0in[0][off] = __float2half(hin);
        }
    }
    gbar();

    // ---- main loop: ONE barrier per iteration: B(t) then A(t+1) ----
#pragma unroll 1
    for (int t = 0; t < NT; t++) {
        const int ping = t & 1;
        const bool validB = (t < L);
        const int tn = t + 1;
        const int nbB = __ldg(&g_nblkE[t]);

        // prefetch pre0[t+1]
        float pf[2][4];
        if (tn < NT) {
            const float* pb = pre0 + ((size_t)(tn * NB + b)) * G4;
#pragma unroll
            for (int nq = 0; nq < 2; nq++)
#pragma unroll
                for (int g = 0; g < 4; g++)
                    pf[nq][g] = __ldg(pb + g * NH + u[nq]);
        }

        // ======== B(t): layer 1 ========
        {
            float gq[2][4];
            run_step<1>(smem, sb, tid, lane, wid, nbB, ping, ping, s_row, wn, gq);
#pragma unroll
            for (int nq = 0; nq < 2; nq++) {
                float iv = sigf(gq[nq][0] + bs1[nq][0]), fv = sigf(gq[nq][1] + bs1[nq][1]);
                float gv = tanhft(gq[nq][2] + bs1[nq][2]), ov = sigf(gq[nq][3] + bs1[nq][3]);
                float cn = fv * c1r[nq] + iv * gv;
                float hn = ov * tanhft(cn);
                c1r[nq] = validB ? cn : c1r[nq];
                float hc = validB ? hn : h1r[nq];
                h1r[nq] = hc;
                float hin = validB ? hn : 0.f;
                size_t off = (size_t)s_row * NH + u[nq];
                g_h1h[ping ^ 1][off] = __float2half(hc);
                g_louth[((size_t)b * NT + t) * NH + u[nq]] = __float2half(hin);
            }
        }

        if (tn < NT) {
            // ======== A(t+1): layer 0 ========
            const bool validA = (tn < L);
            const int nbA = __ldg(&g_nblkE[tn]);
            float gq[2][4];
            run_step<0>(smem, sb, tid, lane, wid, nbA, tn & 1, 0, s_row, wn, gq);
#pragma unroll
            for (int nq = 0; nq < 2; nq++) {
                float iv = sigf(gq[nq][0] + pf[nq][0]), fv = sigf(gq[nq][1] + pf[nq][1]);
                float gv = tanhft(gq[nq][2] + pf[nq][2]), ov = sigf(gq[nq][3] + pf[nq][3]);
                float cn = fv * c0r[nq] + iv * gv;
                float hn = ov * tanhft(cn);
                c0r[nq] = validA ? cn : c0r[nq];
                float hc = validA ? hn : h0r[nq];
                h0r[nq] = hc;
                float hin = validA ? hn : 0.f;
                size_t off = (size_t)s_row * NH + u[nq];
                g_h0h[(tn & 1) ^ 1][off] = __float2half(hc);
                g_h0in[tn & 1][off] = __float2half(hin);
            }
            gbar();
        }
    }

    // ---- final hn/cn (zero-length masked; batch space) ----
    const bool z = (rawL == 0);
#pragma unroll
    for (int nq = 0; nq < 2; nq++) {
        size_t off = (size_t)b * NH + u[nq];
        out_hn[off]           = z ? 0.f : h0r[nq];
        out_cn[off]           = z ? 0.f : c0r[nq];
        out_hn[NB * NH + off] = z ? 0.f : h1r[nq];
        out_cn[NB * NH + off] = z ? 0.f : c1r[nq];
    }
}

// ---------------- entry point ----------------
extern "C" void kernel_launch(void* const* d_in, const int* in_sizes, int n_in,
                              void* d_out, int out_size)
{
    (void)in_sizes; (void)n_in; (void)out_size;
    const float* step_input = (const float*)d_in[0];
    const float* clstm      = (const float*)d_in[1];
    const float* hidden     = (const float*)d_in[2];
    const float* cell       = (const float*)d_in[3];
    const int* lens         = (const int*)d_in[4];
    const float* w_ih0 = (const float*)d_in[5];
    const float* w_hh0 = (const float*)d_in[6];
    const float* b_ih0 = (const float*)d_in[7];
    const float* b_hh0 = (const float*)d_in[8];
    const float* w_ih1 = (const float*)d_in[9];
    const float* w_hh1 = (const float*)d_in[10];
    const float* b_ih1 = (const float*)d_in[11];
    const float* b_hh1 = (const float*)d_in[12];
    const float* w1 = (const float*)d_in[13];
    const float* b1 = (const float*)d_in[14];
    const float* w2 = (const float*)d_in[15];
    const float* b2 = (const float*)d_in[16];

    float* out = (float*)d_out;
    float* out_logits = out;
    float* out_hn = out + (size_t)NB * NT * NO;
    float* out_cn = out_hn + (size_t)NL * NB * NH;

    float* pre0p;
    cudaGetSymbolAddress((void**)&pre0p, g_pre0);
    __half *xhp, *wih0sp, *w1sp, *w2sp, *loutp, *fc1p;
    cudaGetSymbolAddress((void**)&xhp,    g_xh);
    cudaGetSymbolAddress((void**)&wih0sp, g_wih0s);
    cudaGetSymbolAddress((void**)&w1sp,   g_w1s);
    cudaGetSymbolAddress((void**)&w2sp,   g_w2s);
    cudaGetSymbolAddress((void**)&loutp,  g_louth);
    cudaGetSymbolAddress((void**)&fc1p,   g_fc1h);
    const size_t WIH0SZ = (size_t)G4 * NI;
    const size_t W1SZ = (size_t)NH * NH;
    const size_t W2SZ = (size_t)NO * NH;

    cudaFuncSetAttribute(lstm_persist_kernel, cudaFuncAttributeMaxDynamicSharedMemorySize, PERSIST_SMEM);
    cudaFuncSetAttribute(mma_gemm_kernel<0>, cudaFuncAttributeMaxDynamicSharedMemorySize, GEMM_SMEM);
    cudaFuncSetAttribute(mma_gemm_kernel<1>, cudaFuncAttributeMaxDynamicSharedMemorySize, GEMM_SMEM);
    cudaFuncSetAttribute(mma_gemm_kernel<2>, cudaFuncAttributeMaxDynamicSharedMemorySize, GEMM_SMEM);

    // 1) sort + init state + weight/input prep
    sort_kernel<<<1, 256>>>(lens);
    init_state_kernel<<<NL * NB, 256>>>(clstm, hidden, cell, lens);
    prep_w0_kernel<<<4096, 256>>>(w_hh0);
    prep_w1_kernel<<<8192, 256>>>(w_ih1, w_hh1);
    conv_x_kernel<<<8192, 256>>>(step_input);
    conv_w_kernel<<<(int)(WIH0SZ / 1024), 256>>>(w_ih0, wih0sp);
    conv_w_kernel<<<(int)(W1SZ / 1024), 256>>>(w1, w1sp);
    conv_w_kernel<<<(int)(W2SZ / 1024), 256>>>(w2, w2sp);

    // 2) pre0 = x @ Wih0^T + b_ih0 + b_hh0
    mma_gemm_kernel<0><<<dim3(G4 / 128, MROWS / 128), 256, GEMM_SMEM>>>(
        xhp, wih0sp, b_ih0, b_hh0, pre0p, nullptr, G4, NI, nullptr);

    // 3) whole LSTM in one persistent kernel (dynamic-M, weights smem-resident)
    lstm_persist_kernel<<<NCTA, 256, PERSIST_SMEM>>>(lens, pre0p, b_ih1, b_hh1, out_hn, out_cn);

    // 4) FC1: relu(lstm_out @ w1^T + b1) -> fp16
    mma_gemm_kernel<1><<<dim3(NH / 128, MROWS / 128), 256, GEMM_SMEM>>>(
        loutp, w1sp, b1, nullptr, nullptr, fc1p, NH, NH, nullptr);

    // 5) FC2: relu(fc1 @ w2^T + b2), zero-length masked, fp32 out
    mma_gemm_kernel<2><<<dim3(NO / 128, MROWS / 128), 256, GEMM_SMEM>>>(
        fc1p, w2sp, b2, nullptr, out_logits, nullptr, NO, NH, lens);
}

// round 16
// speedup vs baseline: 1.1574x; 1.1574x over previous
#include <cuda_runtime.h>
#include <cuda_fp16.h>
#include <math.h>
#include <stdint.h>

#define NL 2
#define NB 64
#define NT 256
#define NI 512
#define NH 1024
#define NO 256
#define G4 4096
#define MROWS (NB*NT)   // 16384
#define NCTA 128

// ---------------- scratch (device globals) ----------------
__device__ __align__(16) float g_pre0[(size_t)NT*NB*G4];   // [t][b][4H] fp32 (batch space)
__device__ __align__(16) float g_c0[NB*NH], g_c1[NB*NH];   // sorted space
__device__ __align__(16) float g_h0f[NB*NH], g_h1f[NB*NH]; // sorted space
__device__ __align__(16) __half g_h0h[2][NB*NH];   // [ping] sorted space
__device__ __align__(16) __half g_h1h[2][NB*NH];
__device__ __align__(16) __half g_h0in[2][NB*NH];  // [t&1] sorted space
__device__ __align__(16) __half g_w0p[(size_t)G4*NH];       // reordered Whh0 (fp16)
__device__ __align__(16) __half g_w1p[(size_t)G4*2*NH];     // reordered [Wih1|Whh1] (fp16)
// length-sort metadata
__device__ int g_perm[NB];
__device__ int g_Lcs[NB];
__device__ int g_nblkE[NT];
// big-GEMM operands
__device__ __align__(16) __half g_xh[(size_t)MROWS*NI];
__device__ __align__(16) __half g_wih0s[(size_t)G4*NI];
__device__ __align__(16) __half g_w1s[(size_t)NH*NH];
__device__ __align__(16) __half g_w2s[(size_t)NO*NH];
__device__ __align__(16) __half g_louth[(size_t)MROWS*NH];  // batch space rows m=b*256+t
__device__ __align__(16) __half g_fc1h[(size_t)MROWS*NH];
// global barrier state
__device__ unsigned g_gen = 0;
__device__ unsigned g_cnt = 0;

// ---------------- low-level helpers ----------------
__device__ __forceinline__ uint32_t smem_u32(const void* p) {
    uint32_t a;
    asm("{ .reg .u64 t; cvta.to.shared.u64 t, %1; cvt.u32.u64 %0, t; }" : "=r"(a) : "l"(p));
    return a;
}
__device__ __forceinline__ void cpa16(uint32_t dst, const void* src) {
    asm volatile("cp.async.cg.shared.global [%0], [%1], 16;" :: "r"(dst), "l"(src) : "memory");
}
__device__ __forceinline__ void sts128(uint32_t addr, uint4 v) {
    asm volatile("st.shared.v4.b32 [%0], {%1,%2,%3,%4};"
                 :: "r"(addr), "r"(v.x), "r"(v.y), "r"(v.z), "r"(v.w) : "memory");
}
__device__ __forceinline__ void ldmx4(uint32_t* r, uint32_t addr) {
    asm volatile("ldmatrix.sync.aligned.m8n8.x4.shared.b16 {%0,%1,%2,%3}, [%4];"
                 : "=r"(r[0]), "=r"(r[1]), "=r"(r[2]), "=r"(r[3]) : "r"(addr));
}
__device__ __forceinline__ void mma16816(float (&d)[4], const uint32_t* a, const uint32_t* b) {
    asm volatile("mma.sync.aligned.m16n8k16.row.col.f32.f16.f16.f32 "
        "{%0,%1,%2,%3}, {%4,%5,%6,%7}, {%8,%9}, {%0,%1,%2,%3};"
        : "+f"(d[0]), "+f"(d[1]), "+f"(d[2]), "+f"(d[3])
        : "r"(a[0]), "r"(a[1]), "r"(a[2]), "r"(a[3]), "r"(b[0]), "r"(b[1]));
}
__device__ __forceinline__ float sigf(float x)  { return 1.f / (1.f + __expf(-x)); }
__device__ __forceinline__ float tanhft(float x){ return 2.f / (1.f + __expf(-2.f * x)) - 1.f; }

__device__ __forceinline__ unsigned ld_acq(const unsigned* p) {
    unsigned v;
    asm volatile("ld.acquire.gpu.global.u32 %0, [%1];" : "=r"(v) : "l"(p) : "memory");
    return v;
}
// generation barrier; all NCTA CTAs resident
__device__ __forceinline__ void gbar() {
    __syncthreads();
    if (threadIdx.x == 0) {
        unsigned old = ld_acq(&g_gen);
        __threadfence();
        unsigned arr = atomicAdd(&g_cnt, 1u);
        if (arr == NCTA - 1) {
            g_cnt = 0;
            __threadfence();
            atomicAdd(&g_gen, 1u);
        } else {
            while (ld_acq(&g_gen) == old) {}
        }
        __threadfence();
    }
    __syncthreads();
}

// ---------------- sort: perm by clamped length desc + per-step regime ----------------
__global__ void sort_kernel(const int* __restrict__ lens)
{
    __shared__ int Lc[NB], pm[NB], Ls[NB];
    int tid = threadIdx.x;
    if (tid < NB) {
        int L = lens[tid]; if (L < 1) L = 1;
        Lc[tid] = L;
    }
    __syncthreads();
    if (tid < NB) {
        int L = Lc[tid];
        int r = 0;
        for (int j = 0; j < NB; j++) {
            int Lj = Lc[j];
            if (Lj > L || (Lj == L && j < tid)) r++;
        }
        pm[r] = tid;
        Ls[r] = L;
    }
    __syncthreads();
    if (tid < NB) { g_perm[tid] = pm[tid]; g_Lcs[tid] = Ls[tid]; }
    for (int t = tid; t < NT; t += blockDim.x) {
        int a = 0;
        for (int i = 0; i < NB; i++) a += (Ls[i] > t);
        int nb = (a + 15) >> 4;
        if (nb < 1) nb = 1;
        g_nblkE[t] = (nb >= 3) ? 4 : nb;
    }
}

// ---------------- init: weighted hidden + cell copy + fp16 state (sorted space) ----------------
__global__ void init_state_kernel(const float* __restrict__ clstm,
                                  const float* __restrict__ hidden,
                                  const float* __restrict__ cell,
                                  const int* __restrict__ lens)
{
    int l = blockIdx.x >> 6;
    int s = blockIdx.x & 63;
    int b = g_perm[s];
    const float* cl = clstm + (size_t)b * NH;
    const float* hd = hidden + ((size_t)l * NB + b) * NH;
    const float* ce = cell   + ((size_t)l * NB + b) * NH;

    float cmn = 3.4e38f, cmx = -3.4e38f, hmn = 3.4e38f, hmx = -3.4e38f;
    for (int h = threadIdx.x; h < NH; h += 256) {
        float cv = cl[h], hv = hd[h];
        cmn = fminf(cmn, cv); cmx = fmaxf(cmx, cv);
        hmn = fminf(hmn, hv); hmx = fmaxf(hmx, hv);
    }
#pragma unroll
    for (int o = 16; o; o >>= 1) {
        cmn = fminf(cmn, __shfl_xor_sync(0xffffffffu, cmn, o));
        cmx = fmaxf(cmx, __shfl_xor_sync(0xffffffffu, cmx, o));
        hmn = fminf(hmn, __shfl_xor_sync(0xffffffffu, hmn, o));
        hmx = fmaxf(hmx, __shfl_xor_sync(0xffffffffu, hmx, o));
    }
    __shared__ float sm[4][8];
    __shared__ float fs[4];
    int w = threadIdx.x >> 5, ln = threadIdx.x & 31;
    if (ln == 0) { sm[0][w] = cmn; sm[1][w] = cmx; sm[2][w] = hmn; sm[3][w] = hmx; }
    __syncthreads();
    if (threadIdx.x < 4) {
        float v = sm[threadIdx.x][0];
        bool ismin = (threadIdx.x == 0) || (threadIdx.x == 2);
#pragma unroll
        for (int i = 1; i < 8; i++) {
            float x = sm[threadIdx.x][i];
            v = ismin ? fminf(v, x) : fmaxf(v, x);
        }
        fs[threadIdx.x] = v;
    }
    __syncthreads();
    cmn = fs[0]; cmx = fs[1]; hmn = fs[2]; hmx = fs[3];
    float crange = cmx - cmn, hrange = hmx - hmn;
    bool lz = (lens[b] == 0);

    float* hf = l ? g_h1f : g_h0f;
    float* cf = l ? g_c1  : g_c0;
    __half* hh = l ? g_h1h[0] : g_h0h[0];

    for (int h = threadIdx.x; h < NH; h += 256) {
        float cv = cl[h], hv = hd[h];
        float s1 = (crange > 0.f) ? (cv - cmn) / crange : cv;
        float s2 = (hrange > 0.f) ? (hmn + s1 * hrange) : s1;
        float c  = lz ? cv : s2;
        float hw = 0.5f * hv + 0.5f * c;
        size_t off = (size_t)s * NH + h;
        hf[off] = hw;
        cf[off] = ce[h];
        hh[off] = __float2half(hw);
    }
}

// ---------------- step-weight prep: 32 rows/blk, unit-major (uu=r>>2, g=r&3), fp16 ----------------
__global__ void prep_w0_kernel(const float* __restrict__ w)
{
    int idx = blockIdx.x * 256 + threadIdx.x;
    int k = (idx & 255) * 4;
    int row = idx >> 8;
    int blk = row >> 5, r = row & 31;
    int uu = r >> 2, g = r & 3;
    int srow = g * NH + blk * 8 + uu;
    float4 v = *(const float4*)(w + (size_t)srow * NH + k);
    size_t o = (size_t)row * NH + k;
    g_w0p[o + 0] = __float2half(v.x);
    g_w0p[o + 1] = __float2half(v.y);
    g_w0p[o + 2] = __float2half(v.z);
    g_w0p[o + 3] = __float2half(v.w);
}

__global__ void prep_w1_kernel(const float* __restrict__ wih, const float* __restrict__ whh)
{
    int idx = blockIdx.x * 256 + threadIdx.x;
    int k = (idx & 511) * 4;
    int row = idx >> 9;
    int blk = row >> 5, r = row & 31;
    int uu = r >> 2, g = r & 3;
    int srow = g * NH + blk * 8 + uu;
    const float* src = (k < NH) ? (wih + (size_t)srow * NH + k)
                                : (whh + (size_t)srow * NH + (k - NH));
    float4 v = *(const float4*)src;
    size_t o = (size_t)row * (2 * NH) + k;
    g_w1p[o + 0] = __float2half(v.x);
    g_w1p[o + 1] = __float2half(v.y);
    g_w1p[o + 2] = __float2half(v.z);
    g_w1p[o + 3] = __float2half(v.w);
}

// ---------------- fp32 -> fp16 ----------------
__global__ void conv_w_kernel(const float* __restrict__ src, __half* __restrict__ dst)
{
    size_t i = ((size_t)blockIdx.x * 256 + threadIdx.x) * 4;
    float4 v = *(const float4*)(src + i);
    dst[i + 0] = __float2half(v.x);
    dst[i + 1] = __float2half(v.y);
    dst[i + 2] = __float2half(v.z);
    dst[i + 3] = __float2half(v.w);
}

// ---------------- x conversion with reorder: row m = t*64+b ----------------
__global__ void conv_x_kernel(const float* __restrict__ x)
{
    int idx = blockIdx.x * 256 + threadIdx.x;
    int kq = idx & 127;
    int m = idx >> 7;
    int t = m >> 6, b = m & 63;
    float4 v = *(const float4*)(x + ((size_t)b * NT + t) * NI + kq * 4);
    size_t o = (size_t)m * NI + kq * 4;
    g_xh[o + 0] = __float2half(v.x);
    g_xh[o + 1] = __float2half(v.y);
    g_xh[o + 2] = __float2half(v.z);
    g_xh[o + 3] = __float2half(v.w);
}

// ---------------- big MMA GEMM: plain fp16 ----------------
#define GSTAGE 20480
#define GEMM_SMEM (2*GSTAGE)

template<int EP>
__global__ void __launch_bounds__(256) mma_gemm_kernel(
    const __half* __restrict__ A, const __half* __restrict__ W,
    const float* __restrict__ bias, const float* __restrict__ bias2,
    float* __restrict__ Cf, __half* __restrict__ Ch,
    int N, int K, const int* __restrict__ lens)
{
    extern __shared__ char smem[];
    const uint32_t sb = smem_u32(smem);
    const int tid = threadIdx.x;
    const int lane = tid & 31, wid = tid >> 5;
    const int wm = wid & 3, wn = wid >> 2;
    const int n0 = blockIdx.x * 128;
    const int m0 = blockIdx.y * 128;
    const int KC = K >> 5;

    float acc[2][8][4] = {};

    auto issue_load = [&](int c, int stg) {
        const int k0 = c << 5;
        uint32_t base = sb + (uint32_t)stg * GSTAGE;
#pragma unroll
        for (int i = 0; i < 4; i++) {
            int s = tid + (i << 8);
            int p = s >> 9;
            int r = (s >> 2) & 127;
            int seg = s & 3;
            const __half* src = (p == 0) ? A + (size_t)(m0 + r) * K + k0 + seg * 8
                                         : W + (size_t)(n0 + r) * K + k0 + seg * 8;
            cpa16(base + (uint32_t)(p * 10240 + r * 80 + seg * 16), src);
        }
        asm volatile("cp.async.commit_group;" ::: "memory");
    };

    issue_load(0, 0);

    const uint32_t a_base = (uint32_t)((wm * 32 + (lane & 15)) * 80 + (lane >> 4) * 16);
    const uint32_t w_base = (uint32_t)((wn * 64 + (lane & 7) + ((lane >> 4) << 3)) * 80
                                       + ((lane >> 3) & 1) * 16);

    for (int c = 0; c < KC; c++) {
        if (c + 1 < KC) {
            issue_load(c + 1, (c + 1) & 1);
            asm volatile("cp.async.wait_group 1;" ::: "memory");
        } else {
            asm volatile("cp.async.wait_group 0;" ::: "memory");
        }
        __syncthreads();

        uint32_t Ah = sb + (uint32_t)((c & 1) * GSTAGE);
        uint32_t Wh = Ah + 10240;
#pragma unroll
        for (int kk = 0; kk < 2; kk++) {
            uint32_t kb = (uint32_t)kk * 32;
            uint32_t ah[2][4], wh[16];
#pragma unroll
            for (int sub = 0; sub < 2; sub++)
                ldmx4(ah[sub], Ah + a_base + sub * 16 * 80 + kb);
#pragma unroll
            for (int q = 0; q < 4; q++)
                ldmx4(wh + q * 4, Wh + w_base + q * 16 * 80 + kb);
#pragma unroll
            for (int sub = 0; sub < 2; sub++)
#pragma unroll
                for (int nq = 0; nq < 8; nq++)
                    mma16816(acc[sub][nq], ah[sub], wh + nq * 2);
        }
        __syncthreads();
    }

#pragma unroll
    for (int sub = 0; sub < 2; sub++) {
        int r0 = m0 + wm * 32 + sub * 16 + (lane >> 2);
#pragma unroll
        for (int nq = 0; nq < 8; nq++) {
            int c0 = n0 + wn * 64 + nq * 8 + (lane & 3) * 2;
            float b0 = bias[c0], b1 = bias[c0 + 1];
            if (EP == 0) { b0 += bias2[c0]; b1 += bias2[c0 + 1]; }
#pragma unroll
            for (int half_ = 0; half_ < 2; half_++) {
                int r = r0 + half_ * 8;
                float v0 = acc[sub][nq][half_ * 2]     + b0;
                float v1 = acc[sub][nq][half_ * 2 + 1] + b1;
                if (EP >= 1) { v0 = fmaxf(v0, 0.f); v1 = fmaxf(v1, 0.f); }
                if (EP == 2) {
                    if (lens[r >> 8] == 0) { v0 = 0.f; v1 = 0.f; }
                }
                if (EP == 1) {
                    __half2 hp; hp.x = __float2half(v0); hp.y = __float2half(v1);
                    *(__half2*)&Ch[(size_t)r * N + c0] = hp;
                } else {
                    float2 o; o.x = v0; o.y = v1;
                    *(float2*)&Cf[(size_t)r * N + c0] = o;
                }
            }
        }
    }
}

// ---------------- persistent LSTM: smem weights, dynamic-M regimes, 1 barrier/step ----------------
#define A_STG 16384
#define SB_W0 (2*A_STG)           // 32768
#define SB_W1 (SB_W0 + 65536)     // 98304
#define PERSIST_SMEM (SB_W1 + 131072)  // 229376 (224 KB)

// One sub-step GEMM for the CTA's 32 gate rows over active M-blocks.
// NBLKE==4: R14 path (2-stage, shuffle routing).
// NBLKE in {2,1}: split-K across warps + DEEP 4-stage pipeline (3 chunks in flight)
// to keep A-load latency hidden when per-chunk compute is small; smem combine.
template<int LAYER, int NBLKE>
__device__ __forceinline__ void step_core(
    char* smemc, uint32_t sb, int tid, int lane, int wid,
    int ping, int hpar, int s_row, int wn_own, float (&gq)[2][4])
{
    constexpr int NCH = LAYER ? 16 : 8;
    const uint32_t wbase = sb + (LAYER ? SB_W1 : SB_W0);

    auto asrc = [&](int c) -> const __half* {
        if (LAYER == 0)  return g_h0h[ping] + c * 128;
        if (c < 8)       return g_h0in[hpar] + c * 128;
        return g_h1h[ping] + (c - 8) * 128;
    };

    if (NBLKE == 4) {
        const int mb = wid & 3, wnp = wid >> 2;
        const uint32_t arow = (uint32_t)(mb * 16 + (lane & 15));
        const uint32_t arow256 = arow * 256;
        const uint32_t aseg = (uint32_t)(lane >> 4);
        const uint32_t akey = arow & 7;
        const uint32_t wrow = (uint32_t)(wnp * 16 + (lane & 7) + ((lane >> 4) << 3));
        const uint32_t wrow128 = wrow * 128;
        const uint32_t wsub = (uint32_t)(((lane >> 3) & 1) * 16);
        const uint32_t wsw = (wrow & 7) << 4;

        float d[2][4] = {};
        auto issue_load = [&](int c, int stg) {
            const __half* a0 = asrc(c);
            uint32_t base = sb + (uint32_t)stg * A_STG;
#pragma unroll
            for (int i = 0; i < 4; i++) {
                int q = tid + (i << 8);
                int r = q >> 4, sg = q & 15;
                cpa16(base + (uint32_t)(r * 256 + (((sg ^ (r & 7)) << 4))),
                      a0 + (size_t)r * NH + sg * 8);
            }
            asm volatile("cp.async.commit_group;" ::: "memory");
        };
        issue_load(0, 0);
#pragma unroll 1
        for (int c = 0; c < NCH; c++) {
            asm volatile("cp.async.wait_group 0;" ::: "memory");
            __syncthreads();
            if (c + 1 < NCH) issue_load(c + 1, (c + 1) & 1);
            uint32_t Ab = sb + (uint32_t)((c & 1) * A_STG);
            uint32_t Wb = wbase + (uint32_t)(c * 8192);
#pragma unroll
            for (int kq = 0; kq < 8; kq++) {
                uint32_t aaddr = Ab + arow256 + ((((uint32_t)(kq << 1) + aseg) ^ akey) << 4);
                uint32_t waddr = Wb + (uint32_t)((kq >> 2) * 4096) + wrow128
                               + (((uint32_t)((kq & 3) * 32) + wsub) ^ wsw);
                uint32_t ah[4], wh[4];
                ldmx4(ah, aaddr);
                ldmx4(wh, waddr);
                mma16816(d[0], ah, wh);
                mma16816(d[1], ah, wh + 2);
            }
        }
        // register-only quad-pair routing
#pragma unroll
        for (int nq = 0; nq < 2; nq++) {
            float s0 = (lane & 1) ? d[nq][0] : d[nq][2];
            float s1 = (lane & 1) ? d[nq][1] : d[nq][3];
            float r0 = __shfl_xor_sync(0xffffffffu, s0, 1);
            float r1 = __shfl_xor_sync(0xffffffffu, s1, 1);
            if (lane & 1) { gq[nq][2] = d[nq][2]; gq[nq][3] = d[nq][3]; gq[nq][0] = r0; gq[nq][1] = r1; }
            else          { gq[nq][0] = d[nq][0]; gq[nq][1] = d[nq][1]; gq[nq][2] = r0; gq[nq][3] = r1; }
        }
    } else {
        constexpr int NITEMS = 2 * NBLKE;
        constexpr int LOGNI = (NBLKE == 2) ? 2 : 1;
        constexpr int NKQ = NITEMS;
        constexpr int NSPLIT = 8 / NITEMS;
        constexpr uint32_t ASTG_R = (uint32_t)NBLKE * 4096;   // 8KB or 4KB per stage; 4 stages

        const int item = wid & (NITEMS - 1);
        const int ks = wid >> LOGNI;
        const int mb = item >> 1, wnp = item & 1;
        const int kq0 = ks * NKQ;

        const uint32_t arow = (uint32_t)(mb * 16 + (lane & 15));
        const uint32_t arow256 = arow * 256;
        const uint32_t aseg = (uint32_t)(lane >> 4);
        const uint32_t akey = arow & 7;
        const uint32_t wrow = (uint32_t)(wnp * 16 + (lane & 7) + ((lane >> 4) << 3));
        const uint32_t wrow128 = wrow * 128;
        const uint32_t wsub = (uint32_t)(((lane >> 3) & 1) * 16);
        const uint32_t wsw = (wrow & 7) << 4;

        float d[2][4] = {};
        auto issue_load = [&](int c, int stg) {
            const __half* a0 = asrc(c);
            uint32_t base = sb + (uint32_t)stg * ASTG_R;
#pragma unroll
            for (int i = 0; i < NBLKE; i++) {
                int q = tid + (i << 8);
                int r = q >> 4, sg = q & 15;
                cpa16(base + (uint32_t)(r * 256 + (((sg ^ (r & 7)) << 4))),
                      a0 + (size_t)r * NH + sg * 8);
            }
            asm volatile("cp.async.commit_group;" ::: "memory");
        };
        issue_load(0, 0);
        issue_load(1, 1);
        issue_load(2, 2);
#pragma unroll 1
        for (int c = 0; c < NCH; c++) {
            // exact wait ladder: issued = min(NCH, c+3); need chunk c complete
            if (c + 3 <= NCH)      { asm volatile("cp.async.wait_group 2;" ::: "memory"); }
            else if (c + 2 == NCH) { asm volatile("cp.async.wait_group 1;" ::: "memory"); }
            else                   { asm volatile("cp.async.wait_group 0;" ::: "memory"); }
            __syncthreads();
            if (c + 3 < NCH) issue_load(c + 3, (c + 3) & 3);

            uint32_t Ab = sb + (uint32_t)((c & 3) * ASTG_R);
            uint32_t Wb = wbase + (uint32_t)(c * 8192);
#pragma unroll
            for (int i = 0; i < NKQ; i++) {
                int kq = kq0 + i;
                uint32_t aaddr = Ab + arow256 + ((((uint32_t)(kq << 1) + aseg) ^ akey) << 4);
                uint32_t waddr = Wb + (uint32_t)((kq >> 2) * 4096) + wrow128
                               + (((uint32_t)((kq & 3) * 32) + wsub) ^ wsw);
                uint32_t ah[4], wh[4];
                ldmx4(ah, aaddr);
                ldmx4(wh, waddr);
                mma16816(d[0], ah, wh);
                mma16816(d[1], ah, wh + 2);
            }
        }

        // deterministic split-K combine via per-ks smem buffers (overlay A region)
        float* gates = (float*)smemc;                 // [NSPLIT][64][32]
        __syncthreads();                              // all warps done reading A stages
        {
            int row0 = mb * 16 + (lane >> 2);
            int colb = wnp * 16 + (lane & 3) * 2;
            float* gk = gates + ks * 2048;
#pragma unroll
            for (int nq = 0; nq < 2; nq++) {
                int cb = colb + nq * 8;
                gk[row0 * 32 + cb]           = d[nq][0];
                gk[row0 * 32 + cb + 1]       = d[nq][1];
                gk[(row0 + 8) * 32 + cb]     = d[nq][2];
                gk[(row0 + 8) * 32 + cb + 1] = d[nq][3];
            }
        }
        __syncthreads();
#pragma unroll
        for (int nq = 0; nq < 2; nq++) {
            int uloc = wn_own * 4 + nq * 2 + ((lane & 3) >> 1);
            int idx = s_row * 32 + uloc * 4;
#pragma unroll
            for (int g = 0; g < 4; g++) {
                float acc = 0.f;
#pragma unroll
                for (int k = 0; k < NSPLIT; k++)
                    acc += gates[k * 2048 + idx + g];
                gq[nq][g] = acc;
            }
        }
        __syncthreads();   // protect gates region before next sub-step's stage writes
    }
}

template<int LAYER>
__device__ __forceinline__ void run_step(
    char* smemc, uint32_t sb, int tid, int lane, int wid,
    int nblkE, int ping, int hpar, int s_row, int wn_own, float (&gq)[2][4])
{
    if (nblkE == 4)      step_core<LAYER, 4>(smemc, sb, tid, lane, wid, ping, hpar, s_row, wn_own, gq);
    else if (nblkE == 2) step_core<LAYER, 2>(smemc, sb, tid, lane, wid, ping, hpar, s_row, wn_own, gq);
    else                 step_core<LAYER, 1>(smemc, sb, tid, lane, wid, ping, hpar, s_row, wn_own, gq);
}

__global__ void __launch_bounds__(256) lstm_persist_kernel(
    const int* __restrict__ lens,
    const float* __restrict__ pre0,
    const float* __restrict__ bih1, const float* __restrict__ bhh1,
    float* __restrict__ out_hn, float* __restrict__ out_cn)
{
    extern __shared__ char smem[];
    const uint32_t sb = smem_u32(smem);
    const int tid = threadIdx.x;
    const int lane = tid & 31, wid = tid >> 5;
    const int wm = wid & 3, wn = wid >> 2;
    const int blk = blockIdx.x;

    const int s_row = wm * 16 + (lane >> 2) + ((lane & 1) << 3);   // sorted row
    const int b = g_perm[s_row];                                    // batch row
    const int rawL = lens[b];
    const int L = g_Lcs[s_row];

    int u[2];
    u[0] = blk * 8 + wn * 4 + 0 * 2 + ((lane & 3) >> 1);
    u[1] = blk * 8 + wn * 4 + 1 * 2 + ((lane & 3) >> 1);

    // ---- cache both layers' weights in smem (once; 128B-row XOR layout) ----
    {
        const __half* w0 = g_w0p + (size_t)blk * 32 * NH;
#pragma unroll 4
        for (int idx = tid; idx < 4096; idx += 256) {
            int c = idx >> 8;
            int q = idx & 255;
            int r = q >> 3, seg = q & 7;
            uint4 v = *(const uint4*)(w0 + (size_t)r * NH + c * 64 + seg * 8);
            sts128(sb + SB_W0 + (uint32_t)(c * 4096 + r * 128 + ((seg * 16) ^ ((r & 7) << 4))), v);
        }
        const __half* w1 = g_w1p + (size_t)blk * 32 * 2 * NH;
#pragma unroll 4
        for (int idx = tid; idx < 8192; idx += 256) {
            int c = idx >> 8;
            int q = idx & 255;
            int r = q >> 3, seg = q & 7;
            uint4 v = *(const uint4*)(w1 + (size_t)r * 2 * NH + c * 64 + seg * 8);
            sts128(sb + SB_W1 + (uint32_t)(c * 4096 + r * 128 + ((seg * 16) ^ ((r & 7) << 4))), v);
        }
    }
    __syncthreads();

    // load initial states into registers
    float c0r[2], h0r[2], c1r[2], h1r[2];
    float bs1[2][4];
#pragma unroll
    for (int nq = 0; nq < 2; nq++) {
        size_t off = (size_t)s_row * NH + u[nq];
        c0r[nq] = g_c0[off]; h0r[nq] = g_h0f[off];
        c1r[nq] = g_c1[off]; h1r[nq] = g_h1f[off];
#pragma unroll
        for (int g = 0; g < 4; g++)
            bs1[nq][g] = bih1[g * NH + u[nq]] + bhh1[g * NH + u[nq]];
    }

    // ---- prologue: A(0) ----
    {
        float pf[2][4];
        const float* pb = pre0 + ((size_t)(0 * NB + b)) * G4;
#pragma unroll
        for (int nq = 0; nq < 2; nq++)
#pragma unroll
            for (int g = 0; g < 4; g++)
                pf[nq][g] = __ldg(pb + g * NH + u[nq]);
        float gq[2][4];
        run_step<0>(smem, sb, tid, lane, wid, __ldg(&g_nblkE[0]), 0, 0, s_row, wn, gq);
        const bool valid = (0 < L);
#pragma unroll
        for (int nq = 0; nq < 2; nq++) {
            float iv = sigf(gq[nq][0] + pf[nq][0]), fv = sigf(gq[nq][1] + pf[nq][1]);
            float gv = tanhft(gq[nq][2] + pf[nq][2]), ov = sigf(gq[nq][3] + pf[nq][3]);
            float cn = fv * c0r[nq] + iv * gv;
            float hn = ov * tanhft(cn);
            c0r[nq] = valid ? cn : c0r[nq];
            float hc = valid ? hn : h0r[nq];
            h0r[nq] = hc;
            float hin = valid ? hn : 0.f;
            size_t off = (size_t)s_row * NH + u[nq];
            g_h0h[1][off] = __float2half(hc);
            g_h0in[0][off] = __float2half(hin);
        }
    }
    gbar();

    // ---- main loop: ONE barrier per iteration: B(t) then A(t+1) ----
#pragma unroll 1
    for (int t = 0; t < NT; t++) {
        const int ping = t & 1;
        const bool validB = (t < L);
        const int tn = t + 1;
        const int nbB = __ldg(&g_nblkE[t]);

        // prefetch pre0[t+1]
        float pf[2][4];
        if (tn < NT) {
            const float* pb = pre0 + ((size_t)(tn * NB + b)) * G4;
#pragma unroll
            for (int nq = 0; nq < 2; nq++)
#pragma unroll
                for (int g = 0; g < 4; g++)
                    pf[nq][g] = __ldg(pb + g * NH + u[nq]);
        }

        // ======== B(t): layer 1 ========
        {
            float gq[2][4];
            run_step<1>(smem, sb, tid, lane, wid, nbB, ping, ping, s_row, wn, gq);
#pragma unroll
            for (int nq = 0; nq < 2; nq++) {
                float iv = sigf(gq[nq][0] + bs1[nq][0]), fv = sigf(gq[nq][1] + bs1[nq][1]);
                float gv = tanhft(gq[nq][2] + bs1[nq][2]), ov = sigf(gq[nq][3] + bs1[nq][3]);
                float cn = fv * c1r[nq] + iv * gv;
                float hn = ov * tanhft(cn);
                c1r[nq] = validB ? cn : c1r[nq];
                float hc = validB ? hn : h1r[nq];
                h1r[nq] = hc;
                float hin = validB ? hn : 0.f;
                size_t off = (size_t)s_row * NH + u[nq];
                g_h1h[ping ^ 1][off] = __float2half(hc);
                g_louth[((size_t)b * NT + t) * NH + u[nq]] = __float2half(hin);
            }
        }

        if (tn < NT) {
            // ======== A(t+1): layer 0 ========
            const bool validA = (tn < L);
            const int nbA = __ldg(&g_nblkE[tn]);
            float gq[2][4];
            run_step<0>(smem, sb, tid, lane, wid, nbA, tn & 1, 0, s_row, wn, gq);
#pragma unroll
            for (int nq = 0; nq < 2; nq++) {
                float iv = sigf(gq[nq][0] + pf[nq][0]), fv = sigf(gq[nq][1] + pf[nq][1]);
                float gv = tanhft(gq[nq][2] + pf[nq][2]), ov = sigf(gq[nq][3] + pf[nq][3]);
                float cn = fv * c0r[nq] + iv * gv;
                float hn = ov * tanhft(cn);
                c0r[nq] = validA ? cn : c0r[nq];
                float hc = validA ? hn : h0r[nq];
                h0r[nq] = hc;
                float hin = validA ? hn : 0.f;
                size_t off = (size_t)s_row * NH + u[nq];
                g_h0h[(tn & 1) ^ 1][off] = __float2half(hc);
                g_h0in[tn & 1][off] = __float2half(hin);
            }
            gbar();
        }
    }

    // ---- final hn/cn (zero-length masked; batch space) ----
    const bool z = (rawL == 0);
#pragma unroll
    for (int nq = 0; nq < 2; nq++) {
        size_t off = (size_t)b * NH + u[nq];
        out_hn[off]           = z ? 0.f : h0r[nq];
        out_cn[off]           = z ? 0.f : c0r[nq];
        out_hn[NB * NH + off] = z ? 0.f : h1r[nq];
        out_cn[NB * NH + off] = z ? 0.f : c1r[nq];
    }
}

// ---------------- entry point ----------------
extern "C" void kernel_launch(void* const* d_in, const int* in_sizes, int n_in,
                              void* d_out, int out_size)
{
    (void)in_sizes; (void)n_in; (void)out_size;
    const float* step_input = (const float*)d_in[0];
    const float* clstm      = (const float*)d_in[1];
    const float* hidden     = (const float*)d_in[2];
    const float* cell       = (const float*)d_in[3];
    const int* lens         = (const int*)d_in[4];
    const float* w_ih0 = (const float*)d_in[5];
    const float* w_hh0 = (const float*)d_in[6];
    const float* b_ih0 = (const float*)d_in[7];
    const float* b_hh0 = (const float*)d_in[8];
    const float* w_ih1 = (const float*)d_in[9];
    const float* w_hh1 = (const float*)d_in[10];
    const float* b_ih1 = (const float*)d_in[11];
    const float* b_hh1 = (const float*)d_in[12];
    const float* w1 = (const float*)d_in[13];
    const float* b1 = (const float*)d_in[14];
    const float* w2 = (const float*)d_in[15];
    const float* b2 = (const float*)d_in[16];

    float* out = (float*)d_out;
    float* out_logits = out;
    float* out_hn = out + (size_t)NB * NT * NO;
    float* out_cn = out_hn + (size_t)NL * NB * NH;

    float* pre0p;
    cudaGetSymbolAddress((void**)&pre0p, g_pre0);
    __half *xhp, *wih0sp, *w1sp, *w2sp, *loutp, *fc1p;
    cudaGetSymbolAddress((void**)&xhp,    g_xh);
    cudaGetSymbolAddress((void**)&wih0sp, g_wih0s);
    cudaGetSymbolAddress((void**)&w1sp,   g_w1s);
    cudaGetSymbolAddress((void**)&w2sp,   g_w2s);
    cudaGetSymbolAddress((void**)&loutp,  g_louth);
    cudaGetSymbolAddress((void**)&fc1p,   g_fc1h);
    const size_t WIH0SZ = (size_t)G4 * NI;
    const size_t W1SZ = (size_t)NH * NH;
    const size_t W2SZ = (size_t)NO * NH;

    cudaFuncSetAttribute(lstm_persist_kernel, cudaFuncAttributeMaxDynamicSharedMemorySize, PERSIST_SMEM);
    cudaFuncSetAttribute(mma_gemm_kernel<0>, cudaFuncAttributeMaxDynamicSharedMemorySize, GEMM_SMEM);
    cudaFuncSetAttribute(mma_gemm_kernel<1>, cudaFuncAttributeMaxDynamicSharedMemorySize, GEMM_SMEM);
    cudaFuncSetAttribute(mma_gemm_kernel<2>, cudaFuncAttributeMaxDynamicSharedMemorySize, GEMM_SMEM);

    // 1) sort + init state + weight/input prep
    sort_kernel<<<1, 256>>>(lens);
    init_state_kernel<<<NL * NB, 256>>>(clstm, hidden, cell, lens);
    prep_w0_kernel<<<4096, 256>>>(w_hh0);
    prep_w1_kernel<<<8192, 256>>>(w_ih1, w_hh1);
    conv_x_kernel<<<8192, 256>>>(step_input);
    conv_w_kernel<<<(int)(WIH0SZ / 1024), 256>>>(w_ih0, wih0sp);
    conv_w_kernel<<<(int)(W1SZ / 1024), 256>>>(w1, w1sp);
    conv_w_kernel<<<(int)(W2SZ / 1024), 256>>>(w2, w2sp);

    // 2) pre0 = x @ Wih0^T + b_ih0 + b_hh0
    mma_gemm_kernel<0><<<dim3(G4 / 128, MROWS / 128), 256, GEMM_SMEM>>>(
        xhp, wih0sp, b_ih0, b_hh0, pre0p, nullptr, G4, NI, nullptr);

    // 3) whole LSTM in one persistent kernel (dynamic-M + deep tail pipeline)
    lstm_persist_kernel<<<NCTA, 256, PERSIST_SMEM>>>(lens, pre0p, b_ih1, b_hh1, out_hn, out_cn);

    // 4) FC1: relu(lstm_out @ w1^T + b1) -> fp16
    mma_gemm_kernel<1><<<dim3(NH / 128, MROWS / 128), 256, GEMM_SMEM>>>(
        loutp, w1sp, b1, nullptr, nullptr, fc1p, NH, NH, nullptr);

    // 5) FC2: relu(fc1 @ w2^T + b2), zero-length masked, fp32 out
    mma_gemm_kernel<2><<<dim3(NO / 128, MROWS / 128), 256, GEMM_SMEM>>>(
        fc1p, w2sp, b2, nullptr, out_logits, nullptr, NO, NH, lens);
}